// round 1
// baseline (speedup 1.0000x reference)
#include <cuda_runtime.h>
#include <math.h>

#define NN 50000
#define EE 800000
#define GG 128
#define HH 128
#define CC 10

// Scratch (allocation-free contract: __device__ globals)
__device__ float g_agg[NN * HH];
__device__ float g_hA[NN * HH];
__device__ float g_hB[NN * HH];
__device__ float g_pool[GG * HH];
__device__ float g_cnt[GG];

// agg = (1+eps) * in   (folds the self-term so MLP reads only agg)
__global__ void init_agg_kernel(float* __restrict__ agg,
                                const float* __restrict__ in,
                                const float* __restrict__ eps_p) {
    int idx = blockIdx.x * blockDim.x + threadIdx.x;  // over N*H/4
    float e1 = 1.0f + eps_p[0];
    if (idx < NN * HH / 4) {
        float4 v = ((const float4*)in)[idx];
        v.x *= e1; v.y *= e1; v.z *= e1; v.w *= e1;
        ((float4*)agg)[idx] = v;
    }
}

// agg[dst] += in[src] ; one warp per edge (32 lanes x float4 = 128 floats)
__global__ void scatter_kernel(const float* __restrict__ in,
                               float* __restrict__ agg,
                               const int* __restrict__ src,
                               const int* __restrict__ dst) {
    unsigned idx = blockIdx.x * 256u + threadIdx.x;
    unsigned e = idx >> 5;
    unsigned c = (idx & 31u) << 2;
    if (e < EE) {
        int s = src[e];
        int d = dst[e];
        float4 v = *(const float4*)(in + (size_t)s * HH + c);
        atomicAdd((float4*)(agg + (size_t)d * HH + c), v);
    }
}

// Fused: out = relu(BN(relu(relu(A@W1+b1)@W2+b2)))
// 64 rows per block, 256 threads, 8x4 register tile per thread.
// smem: W1(64KB) + W2(64KB) + A-tile(32KB, reused for h1) + params
__global__ __launch_bounds__(256) void mlp_kernel(
    const float* __restrict__ A, float* __restrict__ out,
    const float* __restrict__ W1, const float* __restrict__ b1,
    const float* __restrict__ W2, const float* __restrict__ b2,
    const float* __restrict__ gamma, const float* __restrict__ beta,
    const float* __restrict__ mean, const float* __restrict__ var) {
    extern __shared__ float sm[];
    float* W1s = sm;                 // 16384
    float* W2s = sm + 16384;         // 16384
    float* As  = sm + 32768;         // 8192 (64x128), reused for h1
    float* b1s = sm + 40960;         // 128
    float* b2s = b1s + 128;
    float* scs = b2s + 128;
    float* shs = scs + 128;

    int tid = threadIdx.x;

    {   // stage weights
        const float4* W1v = (const float4*)W1;
        const float4* W2v = (const float4*)W2;
        float4* W1sv = (float4*)W1s;
        float4* W2sv = (float4*)W2s;
        for (int i = tid; i < 4096; i += 256) {
            W1sv[i] = W1v[i];
            W2sv[i] = W2v[i];
        }
        if (tid < 128) {
            b1s[tid] = b1[tid];
            b2s[tid] = b2[tid];
            float sc = gamma[tid] * rsqrtf(var[tid] + 1e-5f);
            scs[tid] = sc;
            shs[tid] = beta[tid] - mean[tid] * sc;
        }
    }

    int rb = blockIdx.x * 64;
    {   // stage A tile (64 rows)
        float4* Asv = (float4*)As;
        for (int i = tid; i < 2048; i += 256) {
            int r = i >> 5;
            int gr = rb + r;
            Asv[i] = (gr < NN) ? ((const float4*)A)[(size_t)gr * 32 + (i & 31)]
                               : make_float4(0.f, 0.f, 0.f, 0.f);
        }
    }
    __syncthreads();

    int tx = tid & 31, ty = tid >> 5;
    int r0 = ty * 8, c0 = tx * 4;

    float acc[8][4];
#pragma unroll
    for (int i = 0; i < 8; i++)
#pragma unroll
        for (int j = 0; j < 4; j++) acc[i][j] = 0.f;

    // GEMM1: h1 = A @ W1
#pragma unroll 4
    for (int k = 0; k < 128; k++) {
        float4 w = *(const float4*)(W1s + k * 128 + c0);
#pragma unroll
        for (int i = 0; i < 8; i++) {
            float a = As[(r0 + i) * 128 + k];
            acc[i][0] += a * w.x;
            acc[i][1] += a * w.y;
            acc[i][2] += a * w.z;
            acc[i][3] += a * w.w;
        }
    }
    __syncthreads();  // all A reads done; reuse As for h1

#pragma unroll
    for (int i = 0; i < 8; i++) {
        float4 h;
        h.x = fmaxf(acc[i][0] + b1s[c0 + 0], 0.f);
        h.y = fmaxf(acc[i][1] + b1s[c0 + 1], 0.f);
        h.z = fmaxf(acc[i][2] + b1s[c0 + 2], 0.f);
        h.w = fmaxf(acc[i][3] + b1s[c0 + 3], 0.f);
        *(float4*)(As + (r0 + i) * 128 + c0) = h;
    }
    __syncthreads();

#pragma unroll
    for (int i = 0; i < 8; i++)
#pragma unroll
        for (int j = 0; j < 4; j++) acc[i][j] = 0.f;

    // GEMM2: h2 = h1 @ W2
#pragma unroll 4
    for (int k = 0; k < 128; k++) {
        float4 w = *(const float4*)(W2s + k * 128 + c0);
#pragma unroll
        for (int i = 0; i < 8; i++) {
            float a = As[(r0 + i) * 128 + k];
            acc[i][0] += a * w.x;
            acc[i][1] += a * w.y;
            acc[i][2] += a * w.z;
            acc[i][3] += a * w.w;
        }
    }

    // epilogue: relu -> BN -> relu, write out
#pragma unroll
    for (int i = 0; i < 8; i++) {
        int gr = rb + r0 + i;
        if (gr < NN) {
            float4 o;
            float v0 = fmaxf(acc[i][0] + b2s[c0 + 0], 0.f);
            float v1 = fmaxf(acc[i][1] + b2s[c0 + 1], 0.f);
            float v2 = fmaxf(acc[i][2] + b2s[c0 + 2], 0.f);
            float v3 = fmaxf(acc[i][3] + b2s[c0 + 3], 0.f);
            o.x = fmaxf(v0 * scs[c0 + 0] + shs[c0 + 0], 0.f);
            o.y = fmaxf(v1 * scs[c0 + 1] + shs[c0 + 1], 0.f);
            o.z = fmaxf(v2 * scs[c0 + 2] + shs[c0 + 2], 0.f);
            o.w = fmaxf(v3 * scs[c0 + 3] + shs[c0 + 3], 0.f);
            *(float4*)(out + (size_t)gr * 128 + c0) = o;
        }
    }
}

__global__ void zero_pool_kernel() {
    for (int i = threadIdx.x; i < GG * HH; i += 256) g_pool[i] = 0.f;
    if (threadIdx.x < GG) g_cnt[threadIdx.x] = 0.f;
}

__global__ void pool_kernel(const float* __restrict__ h,
                            const int* __restrict__ batch) {
    unsigned idx = blockIdx.x * 256u + threadIdx.x;
    unsigned n = idx >> 5;
    unsigned c = (idx & 31u) << 2;
    if (n < NN) {
        int g = batch[n];
        float4 v = *(const float4*)(h + (size_t)n * HH + c);
        atomicAdd((float4*)(g_pool + g * HH + c), v);
        if (c == 0) atomicAdd(&g_cnt[g], 1.0f);
    }
}

__global__ void head_kernel(const float* __restrict__ W1,
                            const float* __restrict__ b1,
                            const float* __restrict__ W2,
                            const float* __restrict__ b2,
                            float* __restrict__ out) {
    int g = blockIdx.x;
    int c = threadIdx.x;  // 128 threads
    __shared__ float p[128];
    __shared__ float z[128];
    float cn = fmaxf(g_cnt[g], 1.0f);
    p[c] = g_pool[g * HH + c] / cn;
    __syncthreads();
    float acc = b1[c];
#pragma unroll 4
    for (int k = 0; k < 128; k++) acc += p[k] * W1[k * 128 + c];
    z[c] = fmaxf(acc, 0.f);
    __syncthreads();
    if (c < CC) {
        float y = b2[c];
#pragma unroll 4
        for (int k = 0; k < 128; k++) y += z[k] * W2[k * CC + c];
        out[g * CC + c] = y;
    }
}

extern "C" void kernel_launch(void* const* d_in, const int* in_sizes, int n_in,
                              void* d_out, int out_size) {
    const float* x     = (const float*)d_in[0];
    const int*   ei    = (const int*)d_in[1];
    const int*   batch = (const int*)d_in[2];
    const float* c1W1  = (const float*)d_in[3];
    const float* c1b1  = (const float*)d_in[4];
    const float* c1W2  = (const float*)d_in[5];
    const float* c1b2  = (const float*)d_in[6];
    const float* c1g   = (const float*)d_in[7];
    const float* c1be  = (const float*)d_in[8];
    const float* c1m   = (const float*)d_in[9];
    const float* c1v   = (const float*)d_in[10];
    const float* c1e   = (const float*)d_in[11];
    const float* csW1  = (const float*)d_in[12];
    const float* csb1  = (const float*)d_in[13];
    const float* csW2  = (const float*)d_in[14];
    const float* csb2  = (const float*)d_in[15];
    const float* csg   = (const float*)d_in[16];
    const float* csbe  = (const float*)d_in[17];
    const float* csm   = (const float*)d_in[18];
    const float* csv   = (const float*)d_in[19];
    const float* cse   = (const float*)d_in[20];
    const float* l1W   = (const float*)d_in[21];
    const float* l1b   = (const float*)d_in[22];
    const float* l2W   = (const float*)d_in[23];
    const float* l2b   = (const float*)d_in[24];
    float* out = (float*)d_out;

    float *agg, *hA, *hB;
    cudaGetSymbolAddress((void**)&agg, g_agg);
    cudaGetSymbolAddress((void**)&hA, g_hA);
    cudaGetSymbolAddress((void**)&hB, g_hB);

    const int SMEM_BYTES = (16384 * 2 + 8192 + 512) * 4;  // 165,888 B
    cudaFuncSetAttribute(mlp_kernel, cudaFuncAttributeMaxDynamicSharedMemorySize,
                         SMEM_BYTES);

    const int INIT_GRID = (NN * HH / 4 + 255) / 256;
    const int SCAT_GRID = (EE * 32) / 256;
    const int MLP_GRID  = (NN + 63) / 64;
    const int POOL_GRID = (NN * 32) / 256;

    for (int i = 0; i < 2; i++) {
        const int* src = ei + (size_t)i * 2 * EE;
        const int* dst = src + EE;
        const float* hin = x + (size_t)i * NN * HH;

        // layer 0 (conv1, per-ensemble weights)
        init_agg_kernel<<<INIT_GRID, 256>>>(agg, hin, c1e + i);
        scatter_kernel<<<SCAT_GRID, 256>>>(hin, agg, src, dst);
        mlp_kernel<<<MLP_GRID, 256, SMEM_BYTES>>>(
            agg, hA,
            c1W1 + (size_t)i * 16384, c1b1 + i * 128,
            c1W2 + (size_t)i * 16384, c1b2 + i * 128,
            c1g + i * 128, c1be + i * 128, c1m + i * 128, c1v + i * 128);

        const float* cur = hA;
        float* nxt = hB;
        for (int l = 0; l < 3; l++) {
            init_agg_kernel<<<INIT_GRID, 256>>>(agg, cur, cse + l);
            scatter_kernel<<<SCAT_GRID, 256>>>(cur, agg, src, dst);
            mlp_kernel<<<MLP_GRID, 256, SMEM_BYTES>>>(
                agg, nxt,
                csW1 + (size_t)l * 16384, csb1 + l * 128,
                csW2 + (size_t)l * 16384, csb2 + l * 128,
                csg + l * 128, csbe + l * 128, csm + l * 128, csv + l * 128);
            const float* t = cur;
            cur = nxt;
            nxt = (float*)t;
        }
        // after 3 swaps cur == hB (final features)

        zero_pool_kernel<<<1, 256>>>();
        pool_kernel<<<POOL_GRID, 256>>>(cur, batch + (size_t)i * NN);
        head_kernel<<<GG, 128>>>(l1W + (size_t)i * 16384, l1b + i * 128,
                                 l2W + (size_t)i * 1280, l2b + i * 10,
                                 out + (size_t)i * GG * CC);
    }
}

// round 2
// speedup vs baseline: 1.4993x; 1.4993x over previous
#include <cuda_runtime.h>
#include <cuda_bf16.h>
#include <math.h>
#include <stdint.h>

#define NN 50000
#define EE 800000
#define GG 128
#define HH 128
#define CC 10

// ---------------- scratch (__device__ globals; no allocs allowed) ------------
__device__ float g_agg[NN * HH];
__device__ float g_hA[NN * HH];
__device__ float g_hB[NN * HH];
__device__ float g_pool[GG * HH];
__device__ float g_cnt[GG];
__device__ int g_rowptr[NN + 1];
__device__ int g_cursor[NN];
__device__ int g_csrsrc[EE];

// ---------------- CSR build ----------------
__global__ void zero_cursor_kernel() {
    int i = blockIdx.x * 256 + threadIdx.x;
    if (i < NN) g_cursor[i] = 0;
}

__global__ void count_kernel(const int* __restrict__ dst) {
    int e = blockIdx.x * 256 + threadIdx.x;
    if (e < EE) atomicAdd(&g_cursor[dst[e]], 1);
}

// single block, 1024 threads: exclusive scan of counts -> rowptr, cursor
__global__ void scan_kernel() {
    __shared__ int wsum[32];
    int tid = threadIdx.x, lane = tid & 31, wid = tid >> 5;
    int carry = 0;
    for (int base = 0; base < NN; base += 1024) {
        int i = base + tid;
        int v = (i < NN) ? g_cursor[i] : 0;
        int x = v;
#pragma unroll
        for (int o = 1; o < 32; o <<= 1) {
            int n = __shfl_up_sync(0xffffffffu, x, o);
            if (lane >= o) x += n;
        }
        if (lane == 31) wsum[wid] = x;
        __syncthreads();
        if (wid == 0) {
            int s = wsum[lane];
#pragma unroll
            for (int o = 1; o < 32; o <<= 1) {
                int n = __shfl_up_sync(0xffffffffu, s, o);
                if (lane >= o) s += n;
            }
            wsum[lane] = s;
        }
        __syncthreads();
        int woff = (wid > 0) ? wsum[wid - 1] : 0;
        int excl = carry + woff + x - v;
        if (i < NN) { g_rowptr[i] = excl; g_cursor[i] = excl; }
        carry += wsum[31];
        __syncthreads();
    }
    if (tid == 0) g_rowptr[NN] = carry;
}

__global__ void fill_kernel(const int* __restrict__ src,
                            const int* __restrict__ dst) {
    int e = blockIdx.x * 256 + threadIdx.x;
    if (e < EE) {
        int d = dst[e];
        int p = atomicAdd(&g_cursor[d], 1);
        g_csrsrc[p] = src[e];
    }
}

// warp per node: agg[n] = (1+eps)*x[n] + sum_{j in N(n)} x[j]
__global__ void agg_kernel(const float* __restrict__ xin,
                           float* __restrict__ agg,
                           const float* __restrict__ eps_p) {
    unsigned idx = blockIdx.x * 256u + threadIdx.x;
    unsigned n = idx >> 5;
    unsigned c = idx & 31u;
    if (n >= NN) return;
    float e1 = 1.0f + eps_p[0];
    const float4* xv = (const float4*)xin;
    float4 s = xv[(size_t)n * 32 + c];
    s.x *= e1; s.y *= e1; s.z *= e1; s.w *= e1;
    int beg = g_rowptr[n], end = g_rowptr[n + 1];
    for (int e = beg; e < end; e++) {
        int sn = __ldg(&g_csrsrc[e]);
        float4 v = xv[(size_t)(unsigned)sn * 32 + c];
        s.x += v.x; s.y += v.y; s.z += v.z; s.w += v.w;
    }
    ((float4*)agg)[(size_t)n * 32 + c] = s;
}

// ---------------- MLP: bf16 split-precision tensor-core GEMM ----------------
// x = hi + lo (bf16 each); D += Ahi*Bhi + Ahi*Blo + Alo*Bhi (fp32 acc)
// smem u32 layout: AH[8704] AL[8704] WH[8704] WL[8704] params[512]
// row stride = 68 u32 (136 bf16) -> all fragment LDS conflict-free.

__device__ __forceinline__ uint32_t pack2(__nv_bfloat16 a, __nv_bfloat16 b) {
    return (uint32_t)__bfloat16_as_ushort(a) |
           ((uint32_t)__bfloat16_as_ushort(b) << 16);
}

__device__ __forceinline__ void bsplit(float v, __nv_bfloat16& h, __nv_bfloat16& l) {
    h = __float2bfloat16_rn(v);
    l = __float2bfloat16_rn(v - __bfloat162float(h));
}

#define MMA16816(c, a0, a1, a2, a3, b0, b1)                                  \
    asm volatile(                                                            \
        "mma.sync.aligned.m16n8k16.row.col.f32.bf16.bf16.f32 "               \
        "{%0,%1,%2,%3}, {%4,%5,%6,%7}, {%8,%9}, {%0,%1,%2,%3};"              \
        : "+f"(c[0]), "+f"(c[1]), "+f"(c[2]), "+f"(c[3])                     \
        : "r"(a0), "r"(a1), "r"(a2), "r"(a3), "r"(b0), "r"(b1))

__device__ __forceinline__ void stage_w(const float* __restrict__ W,
                                        uint32_t* wh, uint32_t* wl, int tid) {
    __nv_bfloat16* whb = (__nv_bfloat16*)wh;
    __nv_bfloat16* wlb = (__nv_bfloat16*)wl;
    const float4* Wv = (const float4*)W;
    for (int idx = tid; idx < 4096; idx += 256) {
        int k = idx >> 5, nq = idx & 31;
        float4 v = Wv[k * 32 + nq];
        float vv[4] = {v.x, v.y, v.z, v.w};
#pragma unroll
        for (int i = 0; i < 4; i++) {
            int n = 4 * nq + i;
            __nv_bfloat16 h, l;
            bsplit(vv[i], h, l);
            whb[n * 136 + k] = h;   // W^T: [n][k], k contiguous
            wlb[n * 136 + k] = l;
        }
    }
}

__device__ __forceinline__ void do_gemm(const uint32_t* __restrict__ AH,
                                        const uint32_t* __restrict__ AL,
                                        const uint32_t* __restrict__ WH,
                                        const uint32_t* __restrict__ WL,
                                        int arow0, int arow8, int tg, int tp,
                                        float acc[16][4]) {
#pragma unroll
    for (int c = 0; c < 8; c++) {
        int ko = tp + 8 * c;
        uint32_t ah0 = AH[arow0 + ko], ah1 = AH[arow8 + ko];
        uint32_t ah2 = AH[arow0 + ko + 4], ah3 = AH[arow8 + ko + 4];
        uint32_t al0 = AL[arow0 + ko], al1 = AL[arow8 + ko];
        uint32_t al2 = AL[arow0 + ko + 4], al3 = AL[arow8 + ko + 4];
#pragma unroll
        for (int j = 0; j < 16; j++) {
            int nb = (8 * j + tg) * 68 + ko;
            uint32_t bh0 = WH[nb], bh1 = WH[nb + 4];
            uint32_t bl0 = WL[nb], bl1 = WL[nb + 4];
            MMA16816(acc[j], ah0, ah1, ah2, ah3, bh0, bh1);
            MMA16816(acc[j], ah0, ah1, ah2, ah3, bl0, bl1);
            MMA16816(acc[j], al0, al1, al2, al3, bh0, bh1);
        }
    }
}

__global__ __launch_bounds__(256) void mlp_kernel(
    const float* __restrict__ A, float* __restrict__ out,
    const float* __restrict__ W1, const float* __restrict__ b1,
    const float* __restrict__ W2, const float* __restrict__ b2,
    const float* __restrict__ gamma, const float* __restrict__ beta,
    const float* __restrict__ mean, const float* __restrict__ var) {
    extern __shared__ uint32_t sm32[];
    uint32_t* AH = sm32;
    uint32_t* AL = sm32 + 8704;
    uint32_t* WH = sm32 + 17408;
    uint32_t* WL = sm32 + 26112;
    float* prm = (float*)(sm32 + 34816);
    float* b1s = prm;
    float* b2s = prm + 128;
    float* scs = prm + 256;
    float* shs = prm + 384;

    int tid = threadIdx.x;
    int w = tid >> 5, t = tid & 31, tg = t >> 2, tp = t & 3;
    int rb = blockIdx.x * 128;

    if (tid < 128) {
        b1s[tid] = b1[tid];
        b2s[tid] = b2[tid];
        float sc = gamma[tid] * rsqrtf(var[tid] + 1e-5f);
        scs[tid] = sc;
        shs[tid] = beta[tid] - mean[tid] * sc;
    }

    // stage A tile (128 rows) split hi/lo
    {
        const float4* Av = (const float4*)A;
        uint2* ahv = (uint2*)AH;
        uint2* alv = (uint2*)AL;
        for (int idx = tid; idx < 4096; idx += 256) {
            int r = idx >> 5, q = idx & 31;
            int gr = rb + r;
            float4 v = (gr < NN) ? Av[(size_t)gr * 32 + q]
                                 : make_float4(0.f, 0.f, 0.f, 0.f);
            __nv_bfloat16 hx, lx, hy, ly, hz, lz, hw, lw;
            bsplit(v.x, hx, lx); bsplit(v.y, hy, ly);
            bsplit(v.z, hz, lz); bsplit(v.w, hw, lw);
            ahv[r * 34 + q] = make_uint2(pack2(hx, hy), pack2(hz, hw));
            alv[r * 34 + q] = make_uint2(pack2(lx, ly), pack2(lz, lw));
        }
    }
    stage_w(W1, WH, WL, tid);
    __syncthreads();

    float acc[16][4];
#pragma unroll
    for (int j = 0; j < 16; j++)
#pragma unroll
        for (int q = 0; q < 4; q++) acc[j][q] = 0.f;

    int row0 = w * 16 + tg;
    int arow0 = row0 * 68, arow8 = arow0 + 8 * 68;

    do_gemm(AH, AL, WH, WL, arow0, arow8, tg, tp, acc);

    // epilogue 1: h1 = relu(acc + b1) -> split bf16 back into AH/AL (own rows)
#pragma unroll
    for (int j = 0; j < 16; j++) {
        int col0 = 8 * j + 2 * tp;
        float bb0 = b1s[col0], bb1 = b1s[col0 + 1];
        float v0 = fmaxf(acc[j][0] + bb0, 0.f);
        float v1 = fmaxf(acc[j][1] + bb1, 0.f);
        float v2 = fmaxf(acc[j][2] + bb0, 0.f);
        float v3 = fmaxf(acc[j][3] + bb1, 0.f);
        __nv_bfloat16 h0, l0, h1b, l1b, h2, l2, h3, l3;
        bsplit(v0, h0, l0); bsplit(v1, h1b, l1b);
        bsplit(v2, h2, l2); bsplit(v3, h3, l3);
        AH[arow0 + 4 * j + tp] = pack2(h0, h1b);
        AL[arow0 + 4 * j + tp] = pack2(l0, l1b);
        AH[arow8 + 4 * j + tp] = pack2(h2, h3);
        AL[arow8 + 4 * j + tp] = pack2(l2, l3);
        acc[j][0] = acc[j][1] = acc[j][2] = acc[j][3] = 0.f;
    }
    __syncthreads();
    stage_w(W2, WH, WL, tid);
    __syncthreads();

    do_gemm(AH, AL, WH, WL, arow0, arow8, tg, tp, acc);

    // final epilogue: relu -> BN -> relu -> global
    int gr0 = rb + row0, gr8 = gr0 + 8;
#pragma unroll
    for (int j = 0; j < 16; j++) {
        int col0 = 8 * j + 2 * tp;
        float bb0 = b2s[col0], bb1 = b2s[col0 + 1];
        float s0 = scs[col0], s1 = scs[col0 + 1];
        float t0 = shs[col0], t1 = shs[col0 + 1];
        float v0 = fmaxf(acc[j][0] + bb0, 0.f);
        float v1 = fmaxf(acc[j][1] + bb1, 0.f);
        float v2 = fmaxf(acc[j][2] + bb0, 0.f);
        float v3 = fmaxf(acc[j][3] + bb1, 0.f);
        float o0 = fmaxf(v0 * s0 + t0, 0.f);
        float o1 = fmaxf(v1 * s1 + t1, 0.f);
        float o2 = fmaxf(v2 * s0 + t0, 0.f);
        float o3 = fmaxf(v3 * s1 + t1, 0.f);
        if (gr0 < NN)
            *(float2*)(out + (size_t)gr0 * HH + col0) = make_float2(o0, o1);
        if (gr8 < NN)
            *(float2*)(out + (size_t)gr8 * HH + col0) = make_float2(o2, o3);
    }
}

// ---------------- pool + head ----------------
__global__ void zero_pool_kernel() {
    int i = blockIdx.x * 256 + threadIdx.x;
    if (i < GG * HH) g_pool[i] = 0.f;
    if (blockIdx.x == 0 && threadIdx.x < GG) g_cnt[threadIdx.x] = 0.f;
}

__global__ void pool_kernel(const float* __restrict__ h,
                            const int* __restrict__ batch) {
    unsigned idx = blockIdx.x * 256u + threadIdx.x;
    unsigned n = idx >> 5;
    unsigned c = (idx & 31u) << 2;
    if (n < NN) {
        int g = batch[n];
        float4 v = *(const float4*)(h + (size_t)n * HH + c);
        atomicAdd((float4*)(g_pool + g * HH + c), v);
        if (c == 0) atomicAdd(&g_cnt[g], 1.0f);
    }
}

__global__ void head_kernel(const float* __restrict__ W1,
                            const float* __restrict__ b1,
                            const float* __restrict__ W2,
                            const float* __restrict__ b2,
                            float* __restrict__ out) {
    int g = blockIdx.x;
    int c = threadIdx.x;  // 128 threads
    __shared__ float p[128];
    __shared__ float z[128];
    float cn = fmaxf(g_cnt[g], 1.0f);
    p[c] = g_pool[g * HH + c] / cn;
    __syncthreads();
    float acc = b1[c];
#pragma unroll 4
    for (int k = 0; k < 128; k++) acc += p[k] * W1[k * 128 + c];
    z[c] = fmaxf(acc, 0.f);
    __syncthreads();
    if (c < CC) {
        float y = b2[c];
#pragma unroll 4
        for (int k = 0; k < 128; k++) y += z[k] * W2[k * CC + c];
        out[g * CC + c] = y;
    }
}

// ---------------- driver ----------------
extern "C" void kernel_launch(void* const* d_in, const int* in_sizes, int n_in,
                              void* d_out, int out_size) {
    const float* x     = (const float*)d_in[0];
    const int*   ei    = (const int*)d_in[1];
    const int*   batch = (const int*)d_in[2];
    const float* c1W1  = (const float*)d_in[3];
    const float* c1b1  = (const float*)d_in[4];
    const float* c1W2  = (const float*)d_in[5];
    const float* c1b2  = (const float*)d_in[6];
    const float* c1g   = (const float*)d_in[7];
    const float* c1be  = (const float*)d_in[8];
    const float* c1m   = (const float*)d_in[9];
    const float* c1v   = (const float*)d_in[10];
    const float* c1e   = (const float*)d_in[11];
    const float* csW1  = (const float*)d_in[12];
    const float* csb1  = (const float*)d_in[13];
    const float* csW2  = (const float*)d_in[14];
    const float* csb2  = (const float*)d_in[15];
    const float* csg   = (const float*)d_in[16];
    const float* csbe  = (const float*)d_in[17];
    const float* csm   = (const float*)d_in[18];
    const float* csv   = (const float*)d_in[19];
    const float* cse   = (const float*)d_in[20];
    const float* l1W   = (const float*)d_in[21];
    const float* l1b   = (const float*)d_in[22];
    const float* l2W   = (const float*)d_in[23];
    const float* l2b   = (const float*)d_in[24];
    float* out = (float*)d_out;

    float *agg, *hA, *hB;
    cudaGetSymbolAddress((void**)&agg, g_agg);
    cudaGetSymbolAddress((void**)&hA, g_hA);
    cudaGetSymbolAddress((void**)&hB, g_hB);

    const int SMEM_BYTES = (34816 + 512) * 4;  // 141,312 B
    cudaFuncSetAttribute(mlp_kernel, cudaFuncAttributeMaxDynamicSharedMemorySize,
                         SMEM_BYTES);

    const int ZC_GRID   = (NN + 255) / 256;
    const int E_GRID    = (EE + 255) / 256;
    const int AGG_GRID  = (NN * 32 + 255) / 256;
    const int MLP_GRID  = (NN + 127) / 128;
    const int POOL_GRID = (NN * 32 + 255) / 256;

    for (int i = 0; i < 2; i++) {
        const int* src = ei + (size_t)i * 2 * EE;
        const int* dst = src + EE;
        const float* hin = x + (size_t)i * NN * HH;

        // build CSR (by dst) for this ensemble's graph
        zero_cursor_kernel<<<ZC_GRID, 256>>>();
        count_kernel<<<E_GRID, 256>>>(dst);
        scan_kernel<<<1, 1024>>>();
        fill_kernel<<<E_GRID, 256>>>(src, dst);

        // layer 0 (conv1, per-ensemble weights)
        agg_kernel<<<AGG_GRID, 256>>>(hin, agg, c1e + i);
        mlp_kernel<<<MLP_GRID, 256, SMEM_BYTES>>>(
            agg, hA,
            c1W1 + (size_t)i * 16384, c1b1 + i * 128,
            c1W2 + (size_t)i * 16384, c1b2 + i * 128,
            c1g + i * 128, c1be + i * 128, c1m + i * 128, c1v + i * 128);

        const float* cur = hA;
        float* nxt = hB;
        for (int l = 0; l < 3; l++) {
            agg_kernel<<<AGG_GRID, 256>>>(cur, agg, cse + l);
            mlp_kernel<<<MLP_GRID, 256, SMEM_BYTES>>>(
                agg, nxt,
                csW1 + (size_t)l * 16384, csb1 + l * 128,
                csW2 + (size_t)l * 16384, csb2 + l * 128,
                csg + l * 128, csbe + l * 128, csm + l * 128, csv + l * 128);
            const float* tswap = cur;
            cur = nxt;
            nxt = (float*)tswap;
        }

        zero_pool_kernel<<<64, 256>>>();
        pool_kernel<<<POOL_GRID, 256>>>(cur, batch + (size_t)i * NN);
        head_kernel<<<GG, 128>>>(l1W + (size_t)i * 16384, l1b + i * 128,
                                 l2W + (size_t)i * 1280, l2b + i * 10,
                                 out + (size_t)i * GG * CC);
    }
}